// round 1
// baseline (speedup 1.0000x reference)
#include <cuda_runtime.h>
#include <math_constants.h>

#define BB 512
#define NNODE 128
#define NRELA 256
#define DD 512
#define D2 1024

// -------------------- scratch (no allocations allowed) --------------------
__device__ float g_hn[BB * D2];   // [node_h | rela_h]
__device__ float g_X1[BB * D2];   // [node_res_ | rela_res_]
__device__ float g_X2[BB * D2];   // [rela_res_ | node_res]
__device__ float g_Y1[BB * D2];   // ng pre-GLU
__device__ float g_Y2[BB * D2];   // rg pre-GLU

// -------------------- fast math helpers --------------------
__device__ __forceinline__ float fast_tanh(float x) {
    // tanh(x) = 1 - 2/(exp(2x)+1); exact at +-inf saturation, ~1e-6 abs err
    float e = __expf(2.0f * x);
    return 1.0f - __fdividef(2.0f, e + 1.0f);
}
__device__ __forceinline__ float fast_sigmoid(float x) {
    return __fdividef(1.0f, 1.0f + __expf(-x));
}

// -------------------- GEMM: C = A @ W + bias --------------------
// Tiles: BM=64, BN=64, BK=16; 128 threads; 8x4 microtile (FFMA-bound).
// W (and bias) may be split into two halves along N at 'nsplit' (each block's
// 64-col range lies entirely within one half since 64 | nsplit).
#define GBM 64
#define GBN 64
#define GBK 16

__global__ __launch_bounds__(128) void gemm_kernel(
    const float* __restrict__ A, int lda,
    const float* __restrict__ W0, const float* __restrict__ W1,
    int nsplit, int ldw,
    const float* __restrict__ bias0, const float* __restrict__ bias1,
    float* __restrict__ C, int ldc, int K)
{
    __shared__ float As[GBK][GBM + 4];   // stride 68 floats (272B, 16B-aligned)
    __shared__ float Ws[GBK][GBN];

    int tid = threadIdx.x;
    int tx = tid & 15;          // 16 col-groups of 4
    int ty = tid >> 4;          // 8 row-groups of 8
    int m0 = blockIdx.y * GBM;
    int n0g = blockIdx.x * GBN;

    const float* Wp;
    const float* bp;
    int n0;
    if (n0g < nsplit) { Wp = W0; bp = bias0; n0 = n0g; }
    else              { Wp = W1; bp = bias1; n0 = n0g - nsplit; }

    float acc[8][4];
#pragma unroll
    for (int i = 0; i < 8; i++)
#pragma unroll
        for (int j = 0; j < 4; j++) acc[i][j] = 0.0f;

    for (int k0 = 0; k0 < K; k0 += GBK) {
        // Load A tile 64x16 (256 float4, 2 per thread), store transposed
#pragma unroll
        for (int i = 0; i < 2; i++) {
            int idx = i * 128 + tid;
            int row = idx >> 2, q = idx & 3;
            float4 v = *(const float4*)(A + (size_t)(m0 + row) * lda + k0 + q * 4);
            As[q * 4 + 0][row] = v.x;
            As[q * 4 + 1][row] = v.y;
            As[q * 4 + 2][row] = v.z;
            As[q * 4 + 3][row] = v.w;
        }
        // Load W tile 16x64 (256 float4, 2 per thread)
#pragma unroll
        for (int i = 0; i < 2; i++) {
            int idx = i * 128 + tid;
            int kk = idx >> 4, nq = idx & 15;
            *(float4*)&Ws[kk][nq * 4] =
                *(const float4*)(Wp + (size_t)(k0 + kk) * ldw + n0 + nq * 4);
        }
        __syncthreads();

#pragma unroll
        for (int kk = 0; kk < GBK; kk++) {
            float a[8], bv[4];
            *(float4*)&a[0] = *(const float4*)&As[kk][ty * 8];
            *(float4*)&a[4] = *(const float4*)&As[kk][ty * 8 + 4];
            *(float4*)&bv[0] = *(const float4*)&Ws[kk][tx * 4];
#pragma unroll
            for (int i = 0; i < 8; i++)
#pragma unroll
                for (int j = 0; j < 4; j++)
                    acc[i][j] = fmaf(a[i], bv[j], acc[i][j]);
        }
        __syncthreads();
    }

    float bv[4];
    *(float4*)bv = *(const float4*)(bp + n0 + tx * 4);
#pragma unroll
    for (int i = 0; i < 8; i++) {
        float4 o;
        o.x = acc[i][0] + bv[0];
        o.y = acc[i][1] + bv[1];
        o.z = acc[i][2] + bv[2];
        o.w = acc[i][3] + bv[3];
        *(float4*)(C + (size_t)(m0 + ty * 8 + i) * ldc + n0g + tx * 4) = o;
    }
}

// -------------------- attention kernel (one block per batch row) --------------------
__global__ __launch_bounds__(512) void attn_kernel(
    const float* __restrict__ p_feats,   // [B, NN, D]
    const float* __restrict__ feats,     // [B, NN, D]
    const float* __restrict__ hn_base,   // [B, D2]
    int hoff,
    const float* __restrict__ w_alpha,   // [D]
    const float* __restrict__ b_alpha,   // scalar
    const int* __restrict__ masks,       // [B, NN]
    float* __restrict__ outp,            // [B, D2]
    int ooff, int NN)
{
    int b = blockIdx.x;
    int tid = threadIdx.x;
    int lane = tid & 31;
    int wid = tid >> 5;

    __shared__ float s_score[NRELA];
    __shared__ float s_red[16];
    __shared__ float s_bcast[2];

    // Per-lane register slices of h-row and w_alpha (d = lane + 32k)
    float hreg[16], wreg[16];
    const float* hrow = hn_base + (size_t)b * D2 + hoff;
#pragma unroll
    for (int k = 0; k < 16; k++) {
        hreg[k] = hrow[lane + 32 * k];
        wreg[k] = w_alpha[lane + 32 * k];
    }
    float balpha = b_alpha[0];

    // ---- phase 1: scores ----
    const float* pbase = p_feats + (size_t)b * NN * DD;
    for (int n = wid; n < NN; n += 16) {
        const float* prow = pbase + (size_t)n * DD;
        float acc = 0.0f;
#pragma unroll
        for (int k = 0; k < 16; k++) {
            float x = prow[lane + 32 * k] + hreg[k];
            acc = fmaf(fast_tanh(x), wreg[k], acc);
        }
#pragma unroll
        for (int o = 16; o; o >>= 1) acc += __shfl_xor_sync(0xffffffffu, acc, o);
        if (lane == 0) s_score[n] = acc + balpha;
    }
    __syncthreads();

    // ---- phase 2: masked softmax ----
    float sc = (tid < NN) ? s_score[tid] : -CUDART_INF_F;
    float mk = (tid < NN) ? (float)masks[(size_t)b * NN + tid] : 0.0f;

    float v = sc;
#pragma unroll
    for (int o = 16; o; o >>= 1) v = fmaxf(v, __shfl_xor_sync(0xffffffffu, v, o));
    if (lane == 0) s_red[wid] = v;
    __syncthreads();
    if (wid == 0) {
        float u = s_red[lane & 15];
#pragma unroll
        for (int o = 8; o; o >>= 1) u = fmaxf(u, __shfl_xor_sync(0xffffffffu, u, o));
        if (lane == 0) s_bcast[0] = u;
    }
    __syncthreads();
    float mx = s_bcast[0];

    float e = (tid < NN) ? mk * __expf(sc - mx) : 0.0f;
    float sv = e;
#pragma unroll
    for (int o = 16; o; o >>= 1) sv += __shfl_xor_sync(0xffffffffu, sv, o);
    __syncthreads();   // s_score reads done; safe to overwrite s_red/s_score
    if (lane == 0) s_red[wid] = sv;
    if (tid < NN) s_score[tid] = e;
    __syncthreads();
    if (wid == 0) {
        float u = (lane < 16) ? s_red[lane] : 0.0f;
#pragma unroll
        for (int o = 8; o; o >>= 1) u += __shfl_xor_sync(0xffffffffu, u, o);
        if (lane == 0) s_bcast[1] = u;
    }
    __syncthreads();
    float denom = s_bcast[1];

    // ---- phase 3: weighted sum ----
    float accum = 0.0f;
    const float* fbase = feats + (size_t)b * NN * DD + tid;
#pragma unroll 8
    for (int n = 0; n < NN; n++) {
        accum = fmaf(s_score[n], fbase[(size_t)n * DD], accum);
    }
    outp[(size_t)b * D2 + ooff + tid] = accum / denom;
}

// -------------------- GLU epilogues --------------------
__global__ __launch_bounds__(256) void glu1_kernel(
    const float* __restrict__ Y1, const float* __restrict__ X1,
    float* __restrict__ outp, float* __restrict__ X2)
{
    int i = blockIdx.x * blockDim.x + threadIdx.x;  // < B*D
    int b = i >> 9, d = i & 511;
    float a = Y1[b * D2 + d];
    float g = Y1[b * D2 + 512 + d];
    float vv = a * fast_sigmoid(g);
    outp[i] = vv;                       // node_res -> out[0:B*D]
    X2[b * D2 + 512 + d] = vv;          // node_res into X2 second half
    X2[b * D2 + d] = X1[b * D2 + 512 + d];  // rela_res_ into X2 first half
}

__global__ __launch_bounds__(256) void glu2_kernel(
    const float* __restrict__ Y2, float* __restrict__ outp)
{
    int i = blockIdx.x * blockDim.x + threadIdx.x;
    int b = i >> 9, d = i & 511;
    float a = Y2[b * D2 + d];
    float g = Y2[b * D2 + 512 + d];
    outp[i] = a * fast_sigmoid(g);      // rela_res -> out[B*D : 2*B*D]
}

// -------------------- launch --------------------
extern "C" void kernel_launch(void* const* d_in, const int* in_sizes, int n_in,
                              void* d_out, int out_size)
{
    const float* h           = (const float*)d_in[0];
    const float* node_feats  = (const float*)d_in[1];
    const float* p_node      = (const float*)d_in[2];
    const float* rela_feats  = (const float*)d_in[3];
    const float* p_rela      = (const float*)d_in[4];
    const int*   att_masks   = (const int*)d_in[5];
    const int*   rela_masks  = (const int*)d_in[6];
    const float* W_h2node    = (const float*)d_in[7];
    const float* b_h2node    = (const float*)d_in[8];
    const float* W_h2rela    = (const float*)d_in[9];
    const float* b_h2rela    = (const float*)d_in[10];
    const float* w_alpha1    = (const float*)d_in[11];
    const float* b_alpha1    = (const float*)d_in[12];
    const float* w_alpha2    = (const float*)d_in[13];
    const float* b_alpha2    = (const float*)d_in[14];
    const float* W_ng        = (const float*)d_in[15];
    const float* b_ng        = (const float*)d_in[16];
    const float* W_rg        = (const float*)d_in[17];
    const float* b_rg        = (const float*)d_in[18];
    float* out = (float*)d_out;

    float *hn, *X1, *X2, *Y1, *Y2;
    cudaGetSymbolAddress((void**)&hn, g_hn);
    cudaGetSymbolAddress((void**)&X1, g_X1);
    cudaGetSymbolAddress((void**)&X2, g_X2);
    cudaGetSymbolAddress((void**)&Y1, g_Y1);
    cudaGetSymbolAddress((void**)&Y2, g_Y2);

    dim3 gthr(128);
    dim3 ggrid(D2 / GBN, BB / GBM);  // (16, 8)
    const int NSPLIT_NONE = 1 << 28;

    // 1) hn = h @ [W_h2node | W_h2rela] + [b_h2node | b_h2rela]
    gemm_kernel<<<ggrid, gthr>>>(h, DD, W_h2node, W_h2rela, DD, DD,
                                 b_h2node, b_h2rela, hn, D2, DD);

    // 2) attention over nodes -> X1[:, 0:512]
    attn_kernel<<<BB, 512>>>(p_node, node_feats, hn, 0,
                             w_alpha1, b_alpha1, att_masks, X1, 0, NNODE);
    // 3) attention over relations -> X1[:, 512:1024]
    attn_kernel<<<BB, 512>>>(p_rela, rela_feats, hn, DD,
                             w_alpha2, b_alpha2, rela_masks, X1, DD, NRELA);

    // 4) Y1 = X1 @ W_ng + b_ng
    gemm_kernel<<<ggrid, gthr>>>(X1, D2, W_ng, W_ng, NSPLIT_NONE, D2,
                                 b_ng, b_ng, Y1, D2, D2);
    // 5) node_res = glu(Y1); build X2 = [rela_res_ | node_res]
    glu1_kernel<<<(BB * DD) / 256, 256>>>(Y1, X1, out, X2);

    // 6) Y2 = X2 @ W_rg + b_rg
    gemm_kernel<<<ggrid, gthr>>>(X2, D2, W_rg, W_rg, NSPLIT_NONE, D2,
                                 b_rg, b_rg, Y2, D2, D2);
    // 7) rela_res = glu(Y2)
    glu2_kernel<<<(BB * DD) / 256, 256>>>(Y2, out + BB * DD);
}

// round 3
// speedup vs baseline: 1.2501x; 1.2501x over previous
#include <cuda_runtime.h>
#include <math_constants.h>

#define BB 512
#define NNODE 128
#define NRELA 256
#define DD 512
#define D2 1024

// -------------------- scratch --------------------
__device__ float g_hn[BB * D2];
__device__ float g_X1[BB * D2];
__device__ float g_X2[BB * D2];
__device__ float g_Y1[BB * D2];
__device__ float g_Y2[BB * D2];

// -------------------- fast math --------------------
__device__ __forceinline__ float tanh_fast(float x) {
    float y; asm("tanh.approx.f32 %0, %1;" : "=f"(y) : "f"(x)); return y;
}
__device__ __forceinline__ float sigmoid_fast(float x) {
    return 0.5f * (1.0f + tanh_fast(0.5f * x));
}
__device__ __forceinline__ unsigned long long pack2(float v) {
    unsigned long long r; asm("mov.b64 %0, {%1, %1};" : "=l"(r) : "f"(v)); return r;
}
__device__ __forceinline__ void ffma2(unsigned long long& acc, unsigned long long a,
                                      unsigned long long b) {
    asm("fma.rn.f32x2 %0, %1, %2, %0;" : "+l"(acc) : "l"(a), "l"(b));
}
__device__ __forceinline__ float lo32(unsigned long long v) {
    return __uint_as_float((unsigned)v);
}
__device__ __forceinline__ float hi32(unsigned long long v) {
    return __uint_as_float((unsigned)(v >> 32));
}

// -------------------- GEMM: C = A @ W + bias --------------------
// BM=BN=64, BK=16, 256 threads, 4x4 microtile via fma.rn.f32x2 (pairs along M).
// Double-buffered smem + global->reg prefetch; one __syncthreads per k-tile.
#define GBM 64
#define GBN 64
#define GBK 16

__global__ __launch_bounds__(256) void gemm_kernel(
    const float* __restrict__ A, int lda,
    const float* __restrict__ W0, const float* __restrict__ W1,
    int nsplit, int ldw,
    const float* __restrict__ bias0, const float* __restrict__ bias1,
    float* __restrict__ C, int ldc, int K)
{
    __shared__ float As[2][GBK][GBM + 4];
    __shared__ float Ws[2][GBK][GBN];

    int tid = threadIdx.x;
    int tx = tid & 15;          // N groups of 4
    int ty = tid >> 4;          // M groups of 4
    int m0 = blockIdx.y * GBM;
    int n0g = blockIdx.x * GBN;

    const float* Wp; const float* bp; int n0;
    if (n0g < nsplit) { Wp = W0; bp = bias0; n0 = n0g; }
    else              { Wp = W1; bp = bias1; n0 = n0g - nsplit; }

    // loader mapping: A tile 64x16 (1 float4/thread), W tile 16x64 (1 float4/thread)
    int arow = tid >> 2, aq = tid & 3;
    int wkk = tid >> 4, wnq = tid & 15;
    const float* Aload = A + (size_t)(m0 + arow) * lda + aq * 4;
    const float* Wload = Wp + (size_t)wkk * ldw + n0 + wnq * 4;

    // preload tile 0
    {
        float4 av = *(const float4*)Aload;
        float4 wv = *(const float4*)Wload;
        As[0][aq * 4 + 0][arow] = av.x;
        As[0][aq * 4 + 1][arow] = av.y;
        As[0][aq * 4 + 2][arow] = av.z;
        As[0][aq * 4 + 3][arow] = av.w;
        *(float4*)&Ws[0][wkk][wnq * 4] = wv;
    }
    __syncthreads();

    unsigned long long acc[2][4];
#pragma unroll
    for (int p = 0; p < 2; p++)
#pragma unroll
        for (int j = 0; j < 4; j++) acc[p][j] = 0ull;

    int ntiles = K / GBK;
    for (int t = 0; t < ntiles; t++) {
        int cur = t & 1;
        float4 av2, wv2;
        if (t + 1 < ntiles) {
            av2 = *(const float4*)(Aload + (t + 1) * GBK);
            wv2 = *(const float4*)(Wload + (size_t)(t + 1) * GBK * ldw);
        }
#pragma unroll
        for (int kk = 0; kk < GBK; kk++) {
            unsigned long long a01 = *(const unsigned long long*)&As[cur][kk][ty * 4];
            unsigned long long a23 = *(const unsigned long long*)&As[cur][kk][ty * 4 + 2];
            float4 bv = *(const float4*)&Ws[cur][kk][tx * 4];
            unsigned long long b0 = pack2(bv.x), b1 = pack2(bv.y);
            unsigned long long b2 = pack2(bv.z), b3 = pack2(bv.w);
            ffma2(acc[0][0], a01, b0); ffma2(acc[0][1], a01, b1);
            ffma2(acc[0][2], a01, b2); ffma2(acc[0][3], a01, b3);
            ffma2(acc[1][0], a23, b0); ffma2(acc[1][1], a23, b1);
            ffma2(acc[1][2], a23, b2); ffma2(acc[1][3], a23, b3);
        }
        if (t + 1 < ntiles) {
            int nxt = cur ^ 1;
            // all threads have finished reading buf[nxt] (tile t-1) before
            // entering this iteration, so stores are safe now
            As[nxt][aq * 4 + 0][arow] = av2.x;
            As[nxt][aq * 4 + 1][arow] = av2.y;
            As[nxt][aq * 4 + 2][arow] = av2.z;
            As[nxt][aq * 4 + 3][arow] = av2.w;
            *(float4*)&Ws[nxt][wkk][wnq * 4] = wv2;
            __syncthreads();
        }
    }

    float bvv[4];
    *(float4*)bvv = *(const float4*)(bp + n0 + tx * 4);
#pragma unroll
    for (int p = 0; p < 2; p++) {
        float4 o0, o1;
        o0.x = lo32(acc[p][0]) + bvv[0]; o1.x = hi32(acc[p][0]) + bvv[0];
        o0.y = lo32(acc[p][1]) + bvv[1]; o1.y = hi32(acc[p][1]) + bvv[1];
        o0.z = lo32(acc[p][2]) + bvv[2]; o1.z = hi32(acc[p][2]) + bvv[2];
        o0.w = lo32(acc[p][3]) + bvv[3]; o1.w = hi32(acc[p][3]) + bvv[3];
        int row = m0 + ty * 4 + p * 2;
        *(float4*)(C + (size_t)row * ldc + n0g + tx * 4) = o0;
        *(float4*)(C + (size_t)(row + 1) * ldc + n0g + tx * 4) = o1;
    }
}

// -------------------- fused attention (node + rela in one grid) --------------------
__global__ __launch_bounds__(512) void attn_kernel(
    const float* __restrict__ p_node, const float* __restrict__ node_feats,
    const float* __restrict__ p_rela, const float* __restrict__ rela_feats,
    const float* __restrict__ hn,
    const float* __restrict__ w_alpha1, const float* __restrict__ b_alpha1,
    const float* __restrict__ w_alpha2, const float* __restrict__ b_alpha2,
    const int* __restrict__ att_masks, const int* __restrict__ rela_masks,
    float* __restrict__ X1)
{
    int bb = blockIdx.x;
    int isR = (bb >= BB) ? 1 : 0;
    int b = isR ? bb - BB : bb;
    int NN = isR ? NRELA : NNODE;
    const float* p_feats = isR ? p_rela : p_node;
    const float* feats   = isR ? rela_feats : node_feats;
    const float* w_alpha = isR ? w_alpha2 : w_alpha1;
    float balpha = isR ? b_alpha2[0] : b_alpha1[0];
    const int* masks = isR ? rela_masks : att_masks;
    int off = isR ? DD : 0;

    int tid = threadIdx.x, lane = tid & 31, wid = tid >> 5;

    __shared__ float s_score[NRELA];
    __shared__ float s_red[16];
    __shared__ float s_bcast[2];

    // register slices (d = lane*4 + c + 128*q)
    float4 h4[4], w4[4];
    const float* hrow = hn + (size_t)b * D2 + off;
#pragma unroll
    for (int q = 0; q < 4; q++) {
        h4[q] = *(const float4*)&hrow[lane * 4 + 128 * q];
        w4[q] = *(const float4*)&w_alpha[lane * 4 + 128 * q];
    }

    // ---- phase 1: scores (one warp per row) ----
    const float* pbase = p_feats + (size_t)b * NN * DD;
    for (int n = wid; n < NN; n += 16) {
        const float* prow = pbase + (size_t)n * DD;
        float acc = 0.0f;
#pragma unroll
        for (int q = 0; q < 4; q++) {
            float4 p = *(const float4*)&prow[lane * 4 + 128 * q];
            acc = fmaf(tanh_fast(p.x + h4[q].x), w4[q].x, acc);
            acc = fmaf(tanh_fast(p.y + h4[q].y), w4[q].y, acc);
            acc = fmaf(tanh_fast(p.z + h4[q].z), w4[q].z, acc);
            acc = fmaf(tanh_fast(p.w + h4[q].w), w4[q].w, acc);
        }
#pragma unroll
        for (int o = 16; o; o >>= 1) acc += __shfl_xor_sync(0xffffffffu, acc, o);
        if (lane == 0) s_score[n] = acc + balpha;
    }
    __syncthreads();

    // ---- phase 2: masked softmax ----
    float sc = (tid < NN) ? s_score[tid] : -CUDART_INF_F;
    float mk = (tid < NN) ? (float)masks[(size_t)b * NN + tid] : 0.0f;

    float v = sc;
#pragma unroll
    for (int o = 16; o; o >>= 1) v = fmaxf(v, __shfl_xor_sync(0xffffffffu, v, o));
    if (lane == 0) s_red[wid] = v;
    __syncthreads();
    if (wid == 0) {
        float u = s_red[lane & 15];
#pragma unroll
        for (int o = 8; o; o >>= 1) u = fmaxf(u, __shfl_xor_sync(0xffffffffu, u, o));
        if (lane == 0) s_bcast[0] = u;
    }
    __syncthreads();
    float mx = s_bcast[0];

    float e = (tid < NN) ? mk * __expf(sc - mx) : 0.0f;
    float sv = e;
#pragma unroll
    for (int o = 16; o; o >>= 1) sv += __shfl_xor_sync(0xffffffffu, sv, o);
    __syncthreads();
    if (lane == 0) s_red[wid] = sv;
    if (tid < NN) s_score[tid] = e;
    __syncthreads();
    if (wid == 0) {
        float u = (lane < 16) ? s_red[lane] : 0.0f;
#pragma unroll
        for (int o = 8; o; o >>= 1) u += __shfl_xor_sync(0xffffffffu, u, o);
        if (lane == 0) s_bcast[1] = u;
    }
    __syncthreads();
    float rden = __fdividef(1.0f, s_bcast[1]);

    // ---- phase 3: weighted sum (coalesced column streaming) ----
    float accum = 0.0f;
    const float* fbase = feats + (size_t)b * NN * DD + tid;
#pragma unroll 8
    for (int n = 0; n < NN; n++) {
        accum = fmaf(s_score[n], fbase[(size_t)n * DD], accum);
    }
    X1[(size_t)b * D2 + off + tid] = accum * rden;
}

// -------------------- GLU epilogues --------------------
__global__ __launch_bounds__(256) void glu1_kernel(
    const float* __restrict__ Y1, const float* __restrict__ X1,
    float* __restrict__ outp, float* __restrict__ X2)
{
    int i = blockIdx.x * blockDim.x + threadIdx.x;
    int b = i >> 9, d = i & 511;
    float a = Y1[b * D2 + d];
    float g = Y1[b * D2 + 512 + d];
    float vv = a * sigmoid_fast(g);
    outp[i] = vv;
    X2[b * D2 + 512 + d] = vv;
    X2[b * D2 + d] = X1[b * D2 + 512 + d];
}

__global__ __launch_bounds__(256) void glu2_kernel(
    const float* __restrict__ Y2, float* __restrict__ outp)
{
    int i = blockIdx.x * blockDim.x + threadIdx.x;
    int b = i >> 9, d = i & 511;
    float a = Y2[b * D2 + d];
    float g = Y2[b * D2 + 512 + d];
    outp[i] = a * sigmoid_fast(g);
}

// -------------------- launch --------------------
extern "C" void kernel_launch(void* const* d_in, const int* in_sizes, int n_in,
                              void* d_out, int out_size)
{
    const float* h           = (const float*)d_in[0];
    const float* node_feats  = (const float*)d_in[1];
    const float* p_node      = (const float*)d_in[2];
    const float* rela_feats  = (const float*)d_in[3];
    const float* p_rela      = (const float*)d_in[4];
    const int*   att_masks   = (const int*)d_in[5];
    const int*   rela_masks  = (const int*)d_in[6];
    const float* W_h2node    = (const float*)d_in[7];
    const float* b_h2node    = (const float*)d_in[8];
    const float* W_h2rela    = (const float*)d_in[9];
    const float* b_h2rela    = (const float*)d_in[10];
    const float* w_alpha1    = (const float*)d_in[11];
    const float* b_alpha1    = (const float*)d_in[12];
    const float* w_alpha2    = (const float*)d_in[13];
    const float* b_alpha2    = (const float*)d_in[14];
    const float* W_ng        = (const float*)d_in[15];
    const float* b_ng        = (const float*)d_in[16];
    const float* W_rg        = (const float*)d_in[17];
    const float* b_rg        = (const float*)d_in[18];
    float* out = (float*)d_out;

    float *hn, *X1, *X2, *Y1, *Y2;
    cudaGetSymbolAddress((void**)&hn, g_hn);
    cudaGetSymbolAddress((void**)&X1, g_X1);
    cudaGetSymbolAddress((void**)&X2, g_X2);
    cudaGetSymbolAddress((void**)&Y1, g_Y1);
    cudaGetSymbolAddress((void**)&Y2, g_Y2);

    dim3 gthr(256);
    dim3 ggrid(D2 / GBN, BB / GBM);  // (16, 8)
    const int NSPLIT_NONE = 1 << 28;

    // 1) hn = h @ [W_h2node | W_h2rela] + bias
    gemm_kernel<<<ggrid, gthr>>>(h, DD, W_h2node, W_h2rela, DD, DD,
                                 b_h2node, b_h2rela, hn, D2, DD);

    // 2) fused attention (node -> X1[:, :512], rela -> X1[:, 512:])
    attn_kernel<<<2 * BB, 512>>>(p_node, node_feats, p_rela, rela_feats, hn,
                                 w_alpha1, b_alpha1, w_alpha2, b_alpha2,
                                 att_masks, rela_masks, X1);

    // 3) Y1 = X1 @ W_ng + b_ng
    gemm_kernel<<<ggrid, gthr>>>(X1, D2, W_ng, W_ng, NSPLIT_NONE, D2,
                                 b_ng, b_ng, Y1, D2, D2);
    // 4) node_res = glu(Y1); X2 = [rela_res_ | node_res]
    glu1_kernel<<<(BB * DD) / 256, 256>>>(Y1, X1, out, X2);

    // 5) Y2 = X2 @ W_rg + b_rg
    gemm_kernel<<<ggrid, gthr>>>(X2, D2, W_rg, W_rg, NSPLIT_NONE, D2,
                                 b_rg, b_rg, Y2, D2, D2);
    // 6) rela_res = glu(Y2)
    glu2_kernel<<<(BB * DD) / 256, 256>>>(Y2, out + BB * DD);
}